// round 14
// baseline (speedup 1.0000x reference)
#include <cuda_runtime.h>
#include <cuda_bf16.h>
#include <math.h>
#include <stdint.h>

#define NTOK 32768      // 32*32*32
#define CDIM 128
#define HEADS 8
#define HD 16
#define CF 512

// ---------------- scratch (device globals) -----------------------------------
__device__ float          g_qkv[384 * NTOK];             // fp32 qkvT [n][384]
__device__ __nv_bfloat16  g_xh[CDIM * NTOK],  g_xl[CDIM * NTOK];   // x split
__device__ __nv_bfloat16  g_ah[CDIM * NTOK],  g_al[CDIM * NTOK];   // attn split
__device__ float          g_x5[CDIM * NTOK];             // proj out fp32
__device__ float          g_t [CDIM * NTOK];             // inorm1 out fp32 (residual)
__device__ __nv_bfloat16  g_th[CDIM * NTOK],  g_tl[CDIM * NTOK];   // t split
__device__ __nv_bfloat16  g_hh[CF * NTOK],    g_hl[CF * NTOK];     // hidden split
__device__ float          g_y [CDIM * NTOK];             // pre-final-IN
// weight splits
__device__ __nv_bfloat16  g_wqh[384 * CDIM], g_wql[384 * CDIM];
__device__ __nv_bfloat16  g_wph[CDIM * CDIM], g_wpl[CDIM * CDIM];
__device__ __nv_bfloat16  g_w1h[CF * CDIM],  g_w1l[CF * CDIM];
__device__ __nv_bfloat16  g_w2h[CDIM * CF],  g_w2l[CDIM * CF];
// instance-norm stats
__device__ float g_sum[CDIM * 8], g_sq[CDIM * 8];
__device__ float g_mean[CDIM], g_rstd[CDIM];

// ---------------- helpers -----------------------------------------------------
__device__ __forceinline__ float gelu_f(float x) {
    const float k0 = 0.7978845608028654f;
    const float k1 = 0.044715f;
    return 0.5f * x * (1.0f + tanhf(k0 * (x + k1 * x * x * x)));
}
__device__ __forceinline__ void splitbf(float v, __nv_bfloat16 &h, __nv_bfloat16 &l) {
    h = __float2bfloat16_rn(v);
    l = __float2bfloat16_rn(v - __bfloat162float(h));
}
__device__ __forceinline__ void ldsm4(unsigned &r0, unsigned &r1, unsigned &r2, unsigned &r3, unsigned addr) {
    asm volatile("ldmatrix.sync.aligned.m8n8.x4.shared.b16 {%0,%1,%2,%3}, [%4];"
                 : "=r"(r0), "=r"(r1), "=r"(r2), "=r"(r3) : "r"(addr));
}
__device__ __forceinline__ void ldsm4t(unsigned &r0, unsigned &r1, unsigned &r2, unsigned &r3, unsigned addr) {
    asm volatile("ldmatrix.sync.aligned.m8n8.x4.trans.shared.b16 {%0,%1,%2,%3}, [%4];"
                 : "=r"(r0), "=r"(r1), "=r"(r2), "=r"(r3) : "r"(addr));
}
__device__ __forceinline__ void mma_bf16(float *c, const unsigned *a, const unsigned *b) {
    asm volatile("mma.sync.aligned.m16n8k16.row.col.f32.bf16.bf16.f32 "
                 "{%0,%1,%2,%3},{%4,%5,%6,%7},{%8,%9},{%0,%1,%2,%3};"
                 : "+f"(c[0]), "+f"(c[1]), "+f"(c[2]), "+f"(c[3])
                 : "r"(a[0]), "r"(a[1]), "r"(a[2]), "r"(a[3]), "r"(b[0]), "r"(b[1]));
}
__device__ __forceinline__ void cp16(uint32_t dst, const void* src) {
    asm volatile("cp.async.cg.shared.global [%0], [%1], 16;" :: "r"(dst), "l"(src));
}
__device__ __forceinline__ void cp_commit() { asm volatile("cp.async.commit_group;" ::: "memory"); }
template<int N>
__device__ __forceinline__ void cp_wait() { asm volatile("cp.async.wait_group %0;" :: "n"(N) : "memory"); }

// ---------------- split kernels (fp32 -> bf16 hi/lo) --------------------------
__device__ __forceinline__ void split4(const float* __restrict__ in,
                                       __nv_bfloat16* __restrict__ h,
                                       __nv_bfloat16* __restrict__ l, int i)
{
    float4 v = ((const float4*)in)[i];
    __nv_bfloat16 h0,h1,h2,h3,l0,l1,l2,l3;
    splitbf(v.x,h0,l0); splitbf(v.y,h1,l1); splitbf(v.z,h2,l2); splitbf(v.w,h3,l3);
    ushort4 hv = { __bfloat16_as_ushort(h0), __bfloat16_as_ushort(h1),
                   __bfloat16_as_ushort(h2), __bfloat16_as_ushort(h3) };
    ushort4 lv = { __bfloat16_as_ushort(l0), __bfloat16_as_ushort(l1),
                   __bfloat16_as_ushort(l2), __bfloat16_as_ushort(l3) };
    ((ushort4*)h)[i] = hv;
    ((ushort4*)l)[i] = lv;
}

__global__ __launch_bounds__(256)
void split_kernel(const float* __restrict__ in, __nv_bfloat16* __restrict__ h,
                  __nv_bfloat16* __restrict__ l, int n4)
{
    int i = blockIdx.x * 256 + threadIdx.x;
    if (i < n4) split4(in, h, l, i);
}

// all 4 weight splits in one launch
__global__ __launch_bounds__(256)
void wsplit_kernel(const float* wq, __nv_bfloat16* wqh, __nv_bfloat16* wql,
                   const float* wp, __nv_bfloat16* wph, __nv_bfloat16* wpl,
                   const float* w1, __nv_bfloat16* w1h, __nv_bfloat16* w1l,
                   const float* w2, __nv_bfloat16* w2h, __nv_bfloat16* w2l)
{
    int b = blockIdx.x;
    if (b < 48)        split4(wq, wqh, wql, b * 256 + threadIdx.x);
    else if (b < 64)   split4(wp, wph, wpl, (b - 48) * 256 + threadIdx.x);
    else if (b < 128)  split4(w1, w1h, w1l, (b - 64) * 256 + threadIdx.x);
    else               split4(w2, w2h, w2l, (b - 128) * 256 + threadIdx.x);
}

// ---------------- tensor-core GEMM (mma.sync, split-bf16, cp.async pipe) -----
// EPI: 0 bias->fp32 [j][n]; 1 gelu->bf16 split; 2 bias+residual->fp32;
//      3 bias->fp32 TRANSPOSED [n][384] (QKV path; outf row stride 384)
#define SW 40    // bf16 row stride of W tiles (32 + 8 pad)
#define SA 136   // bf16 row stride of A tiles (128 + 8 pad)
#define OFF_WH 0
#define OFF_WL 5120
#define OFF_AH 10240
#define OFF_AL 18944
#define ST_BYTES 27648
#define SMEM_TOT (2 * ST_BYTES)
#define TPAD 68  // fp32 transpose row stride (64 + 4), 16B aligned

template<int EPI>
__global__ __launch_bounds__(256)
void gemm_tc(const __nv_bfloat16* __restrict__ Ah, const __nv_bfloat16* __restrict__ Al,
             const __nv_bfloat16* __restrict__ Wh, const __nv_bfloat16* __restrict__ Wl,
             const float* __restrict__ bias, const float* __restrict__ Rres,
             float* __restrict__ outf,
             __nv_bfloat16* __restrict__ outh, __nv_bfloat16* __restrict__ outl,
             int Ktot)
{
    extern __shared__ __align__(16) char smem[];
    const uint32_t sb = (uint32_t)__cvta_generic_to_shared(smem);

    const int tid  = threadIdx.x;
    const int lane = tid & 31;
    const int wid  = tid >> 5;
    const int wm   = wid >> 2;
    const int wn   = wid & 3;
    const int gid  = lane >> 2;
    const int tig  = lane & 3;
    const int lm   = lane & 15;
    const int lq   = lane >> 4;

    const int n0 = blockIdx.x * 128;
    const int j0 = blockIdx.y * 64;

    unsigned aoff[2][2], boff[2][2];
    #pragma unroll
    for (int ma = 0; ma < 2; ma++)
        #pragma unroll
        for (int ka = 0; ka < 2; ka++)
            aoff[ma][ka] = ((wm * 32 + ma * 16 + lm) * SW + ka * 16 + lq * 8) * 2;
    #pragma unroll
    for (int p = 0; p < 2; p++)
        #pragma unroll
        for (int ka = 0; ka < 2; ka++)
            boff[p][ka] = ((ka * 16 + lm) * SA + wn * 32 + p * 16 + lq * 8) * 2;

    const int wjr = tid >> 2, wse = tid & 3;

    float acc[2][4][4];
    #pragma unroll
    for (int a = 0; a < 2; a++)
        #pragma unroll
        for (int b = 0; b < 4; b++)
            #pragma unroll
            for (int c = 0; c < 4; c++) acc[a][b][c] = 0.0f;

    auto prefetch = [&](int ch) {
        const int kc = ch * 32;
        const uint32_t base = sb + (uint32_t)(ch & 1) * ST_BYTES;
        {
            size_t go = (size_t)(j0 + wjr) * Ktot + kc + wse * 8;
            uint32_t so = (uint32_t)((wjr * SW + wse * 8) * 2);
            cp16(base + OFF_WH + so, &Wh[go]);
            cp16(base + OFF_WL + so, &Wl[go]);
        }
        #pragma unroll
        for (int i = 0; i < 2; i++) {
            int flat = tid + i * 256;
            int k = flat >> 4, seg = flat & 15;
            size_t go = (size_t)(kc + k) * NTOK + n0 + seg * 8;
            uint32_t so = (uint32_t)((k * SA + seg * 8) * 2);
            cp16(base + OFF_AH + so, &Ah[go]);
            cp16(base + OFF_AL + so, &Al[go]);
        }
        cp_commit();
    };

    const int nch = Ktot / 32;
    prefetch(0);

    for (int ch = 0; ch < nch; ch++) {
        if (ch + 1 < nch) { prefetch(ch + 1); cp_wait<1>(); }
        else             { cp_wait<0>(); }
        __syncthreads();

        const uint32_t base = sb + (uint32_t)(ch & 1) * ST_BYTES;
        #pragma unroll
        for (int ka = 0; ka < 2; ka++) {
            unsigned ah[2][4], al[2][4], bh[4][2], bl[4][2];
            #pragma unroll
            for (int ma = 0; ma < 2; ma++) {
                ldsm4(ah[ma][0], ah[ma][1], ah[ma][2], ah[ma][3], base + OFF_WH + aoff[ma][ka]);
                ldsm4(al[ma][0], al[ma][1], al[ma][2], al[ma][3], base + OFF_WL + aoff[ma][ka]);
            }
            #pragma unroll
            for (int p = 0; p < 2; p++) {
                unsigned r0, r1, r2, r3;
                ldsm4t(r0, r1, r2, r3, base + OFF_AH + boff[p][ka]);
                bh[2 * p][0] = r0; bh[2 * p][1] = r1;
                bh[2 * p + 1][0] = r2; bh[2 * p + 1][1] = r3;
                ldsm4t(r0, r1, r2, r3, base + OFF_AL + boff[p][ka]);
                bl[2 * p][0] = r0; bl[2 * p][1] = r1;
                bl[2 * p + 1][0] = r2; bl[2 * p + 1][1] = r3;
            }
            #pragma unroll
            for (int ma = 0; ma < 2; ma++)
                #pragma unroll
                for (int na = 0; na < 4; na++) {
                    mma_bf16(acc[ma][na], ah[ma], bh[na]);
                    mma_bf16(acc[ma][na], ah[ma], bl[na]);
                    mma_bf16(acc[ma][na], al[ma], bh[na]);
                }
        }
        __syncthreads();
    }

    if (EPI == 3) {
        // transpose epilogue: stage [n][j] fp32 in smem, write [n][384]
        float* sT = (float*)smem;
        #pragma unroll
        for (int ma = 0; ma < 2; ma++) {
            int jl = wm * 32 + ma * 16 + gid;
            float bA = bias[j0 + jl];
            float bB = bias[j0 + jl + 8];
            #pragma unroll
            for (int na = 0; na < 4; na++) {
                int nl = wn * 32 + na * 8 + tig * 2;
                sT[(nl + 0) * TPAD + jl]     = acc[ma][na][0] + bA;
                sT[(nl + 1) * TPAD + jl]     = acc[ma][na][1] + bA;
                sT[(nl + 0) * TPAD + jl + 8] = acc[ma][na][2] + bB;
                sT[(nl + 1) * TPAD + jl + 8] = acc[ma][na][3] + bB;
            }
        }
        __syncthreads();
        const int row = tid >> 1, half = tid & 1;
        const float4* src = (const float4*)&sT[row * TPAD + half * 32];
        float4* dst = (float4*)&outf[(size_t)(n0 + row) * 384 + j0 + half * 32];
        #pragma unroll
        for (int i = 0; i < 8; i++) dst[i] = src[i];
        return;
    }

    #pragma unroll
    for (int ma = 0; ma < 2; ma++) {
        int jA = j0 + wm * 32 + ma * 16 + gid;
        int jB = jA + 8;
        float bA = bias[jA], bB = bias[jB];
        #pragma unroll
        for (int na = 0; na < 4; na++) {
            int n = n0 + wn * 32 + na * 8 + tig * 2;
            float v0 = acc[ma][na][0] + bA;
            float v1 = acc[ma][na][1] + bA;
            float v2 = acc[ma][na][2] + bB;
            float v3 = acc[ma][na][3] + bB;
            if (EPI == 1) {
                v0 = gelu_f(v0); v1 = gelu_f(v1); v2 = gelu_f(v2); v3 = gelu_f(v3);
                __nv_bfloat16 h0,h1,h2,h3,l0,l1,l2,l3;
                splitbf(v0,h0,l0); splitbf(v1,h1,l1);
                splitbf(v2,h2,l2); splitbf(v3,h3,l3);
                ushort2 hA = { __bfloat16_as_ushort(h0), __bfloat16_as_ushort(h1) };
                ushort2 lA = { __bfloat16_as_ushort(l0), __bfloat16_as_ushort(l1) };
                ushort2 hB = { __bfloat16_as_ushort(h2), __bfloat16_as_ushort(h3) };
                ushort2 lB = { __bfloat16_as_ushort(l2), __bfloat16_as_ushort(l3) };
                *(ushort2*)&outh[(size_t)jA * NTOK + n] = hA;
                *(ushort2*)&outl[(size_t)jA * NTOK + n] = lA;
                *(ushort2*)&outh[(size_t)jB * NTOK + n] = hB;
                *(ushort2*)&outl[(size_t)jB * NTOK + n] = lB;
            } else {
                if (EPI == 2) {
                    float2 rA = *(const float2*)&Rres[(size_t)jA * NTOK + n];
                    float2 rB = *(const float2*)&Rres[(size_t)jB * NTOK + n];
                    v0 += rA.x; v1 += rA.y; v2 += rB.x; v3 += rB.y;
                }
                float2 oA = {v0, v1}, oB = {v2, v3};
                *(float2*)&outf[(size_t)jA * NTOK + n] = oA;
                *(float2*)&outf[(size_t)jB * NTOK + n] = oB;
            }
        }
    }
}

// ---------------- neighborhood attention: qkvT [n][384], float4 loads --------
__global__ __launch_bounds__(256)
void natten_kernel(const float* __restrict__ qkvT,
                   const float* __restrict__ rpb,
                   __nv_bfloat16* __restrict__ outh,
                   __nv_bfloat16* __restrict__ outl)
{
    const int lane = threadIdx.x & 31;
    const int hh   = threadIdx.x >> 5;
    const int ih   = blockIdx.x >> 5;
    const int iw   = blockIdx.x & 31;
    const int iz   = lane;
    const int n    = (ih * 32 + iw) * 32 + iz;

    int sh = ih - 1; sh = sh < 0 ? 0 : (sh > 29 ? 29 : sh);
    int sw = iw - 1; sw = sw < 0 ? 0 : (sw > 29 ? 29 : sw);
    int sz = iz - 1; sz = sz < 0 ? 0 : (sz > 29 ? 29 : sz);

    const float scale = 0.25f;
    float q[HD];
    {
        const float4* qp = (const float4*)&qkvT[(size_t)n * 384 + hh * HD];
        #pragma unroll
        for (int i = 0; i < 4; i++) {
            float4 v = qp[i];
            q[i*4+0] = v.x * scale; q[i*4+1] = v.y * scale;
            q[i*4+2] = v.z * scale; q[i*4+3] = v.w * scale;
        }
    }

    float lg[27];
    float mx = -1e30f;
    #pragma unroll
    for (int a = 0; a < 3; a++)
    #pragma unroll
    for (int b = 0; b < 3; b++) {
        const int nh = sh + a, nw = sw + b;
        const int rowbase = (nh * 32 + nw) * 32;
        const int rh = nh - ih + 2, rw = nw - iw + 2;
        #pragma unroll
        for (int c = 0; c < 3; c++) {
            const int nz = sz + c;
            const float4* kp = (const float4*)&qkvT[(size_t)(rowbase + nz) * 384 + CDIM + hh * HD];
            float s = 0.0f;
            #pragma unroll
            for (int i = 0; i < 4; i++) {
                float4 kv = kp[i];
                s = fmaf(q[i*4+0], kv.x, s);
                s = fmaf(q[i*4+1], kv.y, s);
                s = fmaf(q[i*4+2], kv.z, s);
                s = fmaf(q[i*4+3], kv.w, s);
            }
            const int rz = nz - iz + 2;
            s += rpb[((hh * 5 + rh) * 5 + rw) * 5 + rz];
            lg[(a * 3 + b) * 3 + c] = s;
            mx = fmaxf(mx, s);
        }
    }

    float denom = 0.0f;
    #pragma unroll
    for (int i = 0; i < 27; i++) { lg[i] = __expf(lg[i] - mx); denom += lg[i]; }
    const float inv = 1.0f / denom;

    float o[HD];
    #pragma unroll
    for (int d = 0; d < HD; d++) o[d] = 0.0f;
    #pragma unroll
    for (int a = 0; a < 3; a++)
    #pragma unroll
    for (int b = 0; b < 3; b++) {
        const int rowbase = ((sh + a) * 32 + (sw + b)) * 32;
        #pragma unroll
        for (int c = 0; c < 3; c++) {
            const int nz = sz + c;
            const float w = lg[((a * 3 + b) * 3 + c)] * inv;
            const float4* vp = (const float4*)&qkvT[(size_t)(rowbase + nz) * 384 + 2 * CDIM + hh * HD];
            #pragma unroll
            for (int i = 0; i < 4; i++) {
                float4 vv = vp[i];
                o[i*4+0] = fmaf(w, vv.x, o[i*4+0]);
                o[i*4+1] = fmaf(w, vv.y, o[i*4+1]);
                o[i*4+2] = fmaf(w, vv.z, o[i*4+2]);
                o[i*4+3] = fmaf(w, vv.w, o[i*4+3]);
            }
        }
    }
    #pragma unroll
    for (int d = 0; d < HD; d++) {
        __nv_bfloat16 vh, vl;
        splitbf(o[d], vh, vl);
        outh[(size_t)(hh * HD + d) * NTOK + n] = vh;
        outl[(size_t)(hh * HD + d) * NTOK + n] = vl;
    }
}

// ---------------- instance norm: 3-phase, 1024-way parallel -------------------
__global__ __launch_bounds__(256)
void in_part_kernel(const float* __restrict__ in)
{
    const int c = blockIdx.x >> 3, seg = blockIdx.x & 7;
    const float4* p = (const float4*)(in + (size_t)c * NTOK + seg * 4096);
    float s = 0.0f, s2 = 0.0f;
    #pragma unroll
    for (int i = 0; i < 4; i++) {
        float4 v = p[threadIdx.x + i * 256];
        s  += v.x + v.y + v.z + v.w;
        s2 += v.x * v.x + v.y * v.y + v.z * v.z + v.w * v.w;
    }
    #pragma unroll
    for (int o = 16; o > 0; o >>= 1) {
        s  += __shfl_down_sync(0xffffffffu, s,  o);
        s2 += __shfl_down_sync(0xffffffffu, s2, o);
    }
    __shared__ float rs[8], rq[8];
    if ((threadIdx.x & 31) == 0) { rs[threadIdx.x >> 5] = s; rq[threadIdx.x >> 5] = s2; }
    __syncthreads();
    if (threadIdx.x == 0) {
        float ts = 0.0f, tq = 0.0f;
        #pragma unroll
        for (int i = 0; i < 8; i++) { ts += rs[i]; tq += rq[i]; }
        g_sum[c * 8 + seg] = ts;
        g_sq [c * 8 + seg] = tq;
    }
}

__global__ __launch_bounds__(128)
void in_fin_kernel()
{
    const int c = threadIdx.x;
    float s = 0.0f, s2 = 0.0f;
    #pragma unroll
    for (int i = 0; i < 8; i++) { s += g_sum[c * 8 + i]; s2 += g_sq[c * 8 + i]; }
    float m = s * (1.0f / NTOK);
    float v = s2 * (1.0f / NTOK) - m * m;
    g_mean[c] = m;
    g_rstd[c] = rsqrtf(v + 1e-5f);
}

template<int SPLIT>
__global__ __launch_bounds__(256)
void in_norm_kernel(const float* __restrict__ in, float* __restrict__ out,
                    __nv_bfloat16* __restrict__ oh, __nv_bfloat16* __restrict__ ol)
{
    const int c = blockIdx.x >> 3, seg = blockIdx.x & 7;
    const float m = g_mean[c], r = g_rstd[c];
    const size_t off = (size_t)c * NTOK + seg * 4096;
    const float4* p = (const float4*)(in + off);
    float4* qo = (float4*)(out + off);
    #pragma unroll
    for (int i = 0; i < 4; i++) {
        int idx = threadIdx.x + i * 256;
        float4 v = p[idx];
        v.x = (v.x - m) * r; v.y = (v.y - m) * r;
        v.z = (v.z - m) * r; v.w = (v.w - m) * r;
        qo[idx] = v;
        if (SPLIT) {
            __nv_bfloat16 h0,h1,h2,h3,l0,l1,l2,l3;
            splitbf(v.x,h0,l0); splitbf(v.y,h1,l1); splitbf(v.z,h2,l2); splitbf(v.w,h3,l3);
            ushort4 hv = { __bfloat16_as_ushort(h0), __bfloat16_as_ushort(h1),
                           __bfloat16_as_ushort(h2), __bfloat16_as_ushort(h3) };
            ushort4 lv = { __bfloat16_as_ushort(l0), __bfloat16_as_ushort(l1),
                           __bfloat16_as_ushort(l2), __bfloat16_as_ushort(l3) };
            ((ushort4*)(oh + off))[idx] = hv;
            ((ushort4*)(ol + off))[idx] = lv;
        }
    }
}

// ---------------- launch ------------------------------------------------------
extern "C" void kernel_launch(void* const* d_in, const int* in_sizes, int n_in,
                              void* d_out, int out_size)
{
    (void)in_sizes; (void)n_in; (void)out_size;
    const float* x      = (const float*)d_in[0];
    const float* w_qkv  = (const float*)d_in[1];
    const float* b_qkv  = (const float*)d_in[2];
    const float* rpb    = (const float*)d_in[3];
    const float* w_proj = (const float*)d_in[4];
    const float* b_proj = (const float*)d_in[5];
    const float* w_ffn1 = (const float*)d_in[6];
    const float* b_ffn1 = (const float*)d_in[7];
    const float* w_ffn2 = (const float*)d_in[8];
    const float* b_ffn2 = (const float*)d_in[9];
    float* out = (float*)d_out;

    float *qkv, *x5, *t, *y;
    __nv_bfloat16 *xh,*xl,*ah,*al,*th,*tl,*hh,*hl;
    __nv_bfloat16 *wqh,*wql,*wph,*wpl,*w1h,*w1l,*w2h,*w2l;
    cudaGetSymbolAddress((void**)&qkv, g_qkv);
    cudaGetSymbolAddress((void**)&x5,  g_x5);
    cudaGetSymbolAddress((void**)&t,   g_t);
    cudaGetSymbolAddress((void**)&y,   g_y);
    cudaGetSymbolAddress((void**)&xh,  g_xh);  cudaGetSymbolAddress((void**)&xl, g_xl);
    cudaGetSymbolAddress((void**)&ah,  g_ah);  cudaGetSymbolAddress((void**)&al, g_al);
    cudaGetSymbolAddress((void**)&th,  g_th);  cudaGetSymbolAddress((void**)&tl, g_tl);
    cudaGetSymbolAddress((void**)&hh,  g_hh);  cudaGetSymbolAddress((void**)&hl, g_hl);
    cudaGetSymbolAddress((void**)&wqh, g_wqh); cudaGetSymbolAddress((void**)&wql, g_wql);
    cudaGetSymbolAddress((void**)&wph, g_wph); cudaGetSymbolAddress((void**)&wpl, g_wpl);
    cudaGetSymbolAddress((void**)&w1h, g_w1h); cudaGetSymbolAddress((void**)&w1l, g_w1l);
    cudaGetSymbolAddress((void**)&w2h, g_w2h); cudaGetSymbolAddress((void**)&w2l, g_w2l);

    cudaFuncSetAttribute(gemm_tc<0>, cudaFuncAttributeMaxDynamicSharedMemorySize, SMEM_TOT);
    cudaFuncSetAttribute(gemm_tc<1>, cudaFuncAttributeMaxDynamicSharedMemorySize, SMEM_TOT);
    cudaFuncSetAttribute(gemm_tc<2>, cudaFuncAttributeMaxDynamicSharedMemorySize, SMEM_TOT);
    cudaFuncSetAttribute(gemm_tc<3>, cudaFuncAttributeMaxDynamicSharedMemorySize, SMEM_TOT);

    // 0) splits: x + all weights (one launch)
    split_kernel<<<4096, 256>>>(x, xh, xl, CDIM * NTOK / 4);
    wsplit_kernel<<<192, 256>>>(w_qkv, wqh, wql, w_proj, wph, wpl,
                                w_ffn1, w1h, w1l, w_ffn2, w2h, w2l);

    // 1) QKV -> fp32 TRANSPOSED [n][384]
    gemm_tc<3><<<dim3(NTOK / 128, 384 / 64), 256, SMEM_TOT>>>(
        xh, xl, wqh, wql, b_qkv, nullptr, qkv, nullptr, nullptr, CDIM);
    // 2) natten (d-contiguous loads) -> attn split bf16 [c][n]
    natten_kernel<<<1024, 256>>>(qkv, rpb, ah, al);
    // 3) proj -> x5 fp32
    gemm_tc<0><<<dim3(NTOK / 128, 128 / 64), 256, SMEM_TOT>>>(
        ah, al, wph, wpl, b_proj, nullptr, x5, nullptr, nullptr, CDIM);
    // 4) inorm1 -> t fp32 + split
    in_part_kernel<<<1024, 256>>>(x5);
    in_fin_kernel<<<1, 128>>>();
    in_norm_kernel<1><<<1024, 256>>>(x5, t, th, tl);
    // 5) FFN1 + gelu -> hidden split bf16
    gemm_tc<1><<<dim3(NTOK / 128, 512 / 64), 256, SMEM_TOT>>>(
        th, tl, w1h, w1l, b_ffn1, nullptr, nullptr, hh, hl, CDIM);
    // 6) FFN2 + residual(t) -> y fp32
    gemm_tc<2><<<dim3(NTOK / 128, 128 / 64), 256, SMEM_TOT>>>(
        hh, hl, w2h, w2l, b_ffn2, t, y, nullptr, nullptr, CF);
    // 7) final inorm -> out
    in_part_kernel<<<1024, 256>>>(y);
    in_fin_kernel<<<1, 128>>>();
    in_norm_kernel<0><<<1024, 256>>>(y, out, nullptr, nullptr);
}

// round 16
// speedup vs baseline: 1.6171x; 1.6171x over previous
#include <cuda_runtime.h>
#include <cuda_bf16.h>
#include <math.h>
#include <stdint.h>

#define NTOK 32768      // 32*32*32
#define CDIM 128
#define HEADS 8
#define HD 16
#define CF 512

// ---------------- scratch (device globals) -----------------------------------
__device__ float          g_qkv[384 * NTOK];             // fp32 qkv [j][n]
__device__ __nv_bfloat16  g_xh[CDIM * NTOK],  g_xl[CDIM * NTOK];   // x split
__device__ __nv_bfloat16  g_ah[CDIM * NTOK],  g_al[CDIM * NTOK];   // attn split
__device__ float          g_x5[CDIM * NTOK];             // proj out fp32
__device__ float          g_t [CDIM * NTOK];             // inorm1 out fp32 (residual)
__device__ __nv_bfloat16  g_th[CDIM * NTOK],  g_tl[CDIM * NTOK];   // t split
__device__ __nv_bfloat16  g_hh[CF * NTOK],    g_hl[CF * NTOK];     // hidden split
__device__ float          g_y [CDIM * NTOK];             // pre-final-IN
// weight splits
__device__ __nv_bfloat16  g_wqh[384 * CDIM], g_wql[384 * CDIM];
__device__ __nv_bfloat16  g_wph[CDIM * CDIM], g_wpl[CDIM * CDIM];
__device__ __nv_bfloat16  g_w1h[CF * CDIM],  g_w1l[CF * CDIM];
__device__ __nv_bfloat16  g_w2h[CDIM * CF],  g_w2l[CDIM * CF];
// instance-norm stats
__device__ float g_sum[CDIM * 8], g_sq[CDIM * 8];
__device__ float g_mean[CDIM], g_rstd[CDIM];

// ---------------- helpers -----------------------------------------------------
__device__ __forceinline__ float gelu_f(float x) {
    const float k0 = 0.7978845608028654f;
    const float k1 = 0.044715f;
    return 0.5f * x * (1.0f + tanhf(k0 * (x + k1 * x * x * x)));
}
__device__ __forceinline__ void splitbf(float v, __nv_bfloat16 &h, __nv_bfloat16 &l) {
    h = __float2bfloat16_rn(v);
    l = __float2bfloat16_rn(v - __bfloat162float(h));
}
__device__ __forceinline__ void ldsm4(unsigned &r0, unsigned &r1, unsigned &r2, unsigned &r3, unsigned addr) {
    asm volatile("ldmatrix.sync.aligned.m8n8.x4.shared.b16 {%0,%1,%2,%3}, [%4];"
                 : "=r"(r0), "=r"(r1), "=r"(r2), "=r"(r3) : "r"(addr));
}
__device__ __forceinline__ void ldsm4t(unsigned &r0, unsigned &r1, unsigned &r2, unsigned &r3, unsigned addr) {
    asm volatile("ldmatrix.sync.aligned.m8n8.x4.trans.shared.b16 {%0,%1,%2,%3}, [%4];"
                 : "=r"(r0), "=r"(r1), "=r"(r2), "=r"(r3) : "r"(addr));
}
__device__ __forceinline__ void mma_bf16(float *c, const unsigned *a, const unsigned *b) {
    asm volatile("mma.sync.aligned.m16n8k16.row.col.f32.bf16.bf16.f32 "
                 "{%0,%1,%2,%3},{%4,%5,%6,%7},{%8,%9},{%0,%1,%2,%3};"
                 : "+f"(c[0]), "+f"(c[1]), "+f"(c[2]), "+f"(c[3])
                 : "r"(a[0]), "r"(a[1]), "r"(a[2]), "r"(a[3]), "r"(b[0]), "r"(b[1]));
}
__device__ __forceinline__ void cp16(uint32_t dst, const void* src) {
    asm volatile("cp.async.cg.shared.global [%0], [%1], 16;" :: "r"(dst), "l"(src));
}
__device__ __forceinline__ void cp_commit() { asm volatile("cp.async.commit_group;" ::: "memory"); }
template<int N>
__device__ __forceinline__ void cp_wait() { asm volatile("cp.async.wait_group %0;" :: "n"(N) : "memory"); }

// ---------------- split kernels (fp32 -> bf16 hi/lo) --------------------------
__device__ __forceinline__ void split4(const float* __restrict__ in,
                                       __nv_bfloat16* __restrict__ h,
                                       __nv_bfloat16* __restrict__ l, int i)
{
    float4 v = ((const float4*)in)[i];
    __nv_bfloat16 h0,h1,h2,h3,l0,l1,l2,l3;
    splitbf(v.x,h0,l0); splitbf(v.y,h1,l1); splitbf(v.z,h2,l2); splitbf(v.w,h3,l3);
    ushort4 hv = { __bfloat16_as_ushort(h0), __bfloat16_as_ushort(h1),
                   __bfloat16_as_ushort(h2), __bfloat16_as_ushort(h3) };
    ushort4 lv = { __bfloat16_as_ushort(l0), __bfloat16_as_ushort(l1),
                   __bfloat16_as_ushort(l2), __bfloat16_as_ushort(l3) };
    ((ushort4*)h)[i] = hv;
    ((ushort4*)l)[i] = lv;
}

__global__ __launch_bounds__(256)
void split_kernel(const float* __restrict__ in, __nv_bfloat16* __restrict__ h,
                  __nv_bfloat16* __restrict__ l, int n4)
{
    int i = blockIdx.x * 256 + threadIdx.x;
    if (i < n4) split4(in, h, l, i);
}

__global__ __launch_bounds__(256)
void wsplit_kernel(const float* wq, __nv_bfloat16* wqh, __nv_bfloat16* wql,
                   const float* wp, __nv_bfloat16* wph, __nv_bfloat16* wpl,
                   const float* w1, __nv_bfloat16* w1h, __nv_bfloat16* w1l,
                   const float* w2, __nv_bfloat16* w2h, __nv_bfloat16* w2l)
{
    int b = blockIdx.x;
    if (b < 48)        split4(wq, wqh, wql, b * 256 + threadIdx.x);
    else if (b < 64)   split4(wp, wph, wpl, (b - 48) * 256 + threadIdx.x);
    else if (b < 128)  split4(w1, w1h, w1l, (b - 64) * 256 + threadIdx.x);
    else               split4(w2, w2h, w2l, (b - 128) * 256 + threadIdx.x);
}

// ---------------- tensor-core GEMM (mma.sync, split-bf16, cp.async pipe) -----
#define SW 40    // bf16 row stride of W tiles (32 + 8 pad)
#define SA 136   // bf16 row stride of A tiles (128 + 8 pad)
#define OFF_WH 0
#define OFF_WL 5120
#define OFF_AH 10240
#define OFF_AL 18944
#define ST_BYTES 27648
#define SMEM_TOT (2 * ST_BYTES)

template<int EPI>
__global__ __launch_bounds__(256)
void gemm_tc(const __nv_bfloat16* __restrict__ Ah, const __nv_bfloat16* __restrict__ Al,
             const __nv_bfloat16* __restrict__ Wh, const __nv_bfloat16* __restrict__ Wl,
             const float* __restrict__ bias, const float* __restrict__ Rres,
             float* __restrict__ outf,
             __nv_bfloat16* __restrict__ outh, __nv_bfloat16* __restrict__ outl,
             int Ktot)
{
    extern __shared__ __align__(16) char smem[];
    const uint32_t sb = (uint32_t)__cvta_generic_to_shared(smem);

    const int tid  = threadIdx.x;
    const int lane = tid & 31;
    const int wid  = tid >> 5;
    const int wm   = wid >> 2;
    const int wn   = wid & 3;
    const int gid  = lane >> 2;
    const int tig  = lane & 3;
    const int lm   = lane & 15;
    const int lq   = lane >> 4;

    const int n0 = blockIdx.x * 128;
    const int j0 = blockIdx.y * 64;

    unsigned aoff[2][2], boff[2][2];
    #pragma unroll
    for (int ma = 0; ma < 2; ma++)
        #pragma unroll
        for (int ka = 0; ka < 2; ka++)
            aoff[ma][ka] = ((wm * 32 + ma * 16 + lm) * SW + ka * 16 + lq * 8) * 2;
    #pragma unroll
    for (int p = 0; p < 2; p++)
        #pragma unroll
        for (int ka = 0; ka < 2; ka++)
            boff[p][ka] = ((ka * 16 + lm) * SA + wn * 32 + p * 16 + lq * 8) * 2;

    const int wjr = tid >> 2, wse = tid & 3;

    float acc[2][4][4];
    #pragma unroll
    for (int a = 0; a < 2; a++)
        #pragma unroll
        for (int b = 0; b < 4; b++)
            #pragma unroll
            for (int c = 0; c < 4; c++) acc[a][b][c] = 0.0f;

    auto prefetch = [&](int ch) {
        const int kc = ch * 32;
        const uint32_t base = sb + (uint32_t)(ch & 1) * ST_BYTES;
        {
            size_t go = (size_t)(j0 + wjr) * Ktot + kc + wse * 8;
            uint32_t so = (uint32_t)((wjr * SW + wse * 8) * 2);
            cp16(base + OFF_WH + so, &Wh[go]);
            cp16(base + OFF_WL + so, &Wl[go]);
        }
        #pragma unroll
        for (int i = 0; i < 2; i++) {
            int flat = tid + i * 256;
            int k = flat >> 4, seg = flat & 15;
            size_t go = (size_t)(kc + k) * NTOK + n0 + seg * 8;
            uint32_t so = (uint32_t)((k * SA + seg * 8) * 2);
            cp16(base + OFF_AH + so, &Ah[go]);
            cp16(base + OFF_AL + so, &Al[go]);
        }
        cp_commit();
    };

    const int nch = Ktot / 32;
    prefetch(0);

    for (int ch = 0; ch < nch; ch++) {
        if (ch + 1 < nch) { prefetch(ch + 1); cp_wait<1>(); }
        else             { cp_wait<0>(); }
        __syncthreads();

        const uint32_t base = sb + (uint32_t)(ch & 1) * ST_BYTES;
        #pragma unroll
        for (int ka = 0; ka < 2; ka++) {
            unsigned ah[2][4], al[2][4], bh[4][2], bl[4][2];
            #pragma unroll
            for (int ma = 0; ma < 2; ma++) {
                ldsm4(ah[ma][0], ah[ma][1], ah[ma][2], ah[ma][3], base + OFF_WH + aoff[ma][ka]);
                ldsm4(al[ma][0], al[ma][1], al[ma][2], al[ma][3], base + OFF_WL + aoff[ma][ka]);
            }
            #pragma unroll
            for (int p = 0; p < 2; p++) {
                unsigned r0, r1, r2, r3;
                ldsm4t(r0, r1, r2, r3, base + OFF_AH + boff[p][ka]);
                bh[2 * p][0] = r0; bh[2 * p][1] = r1;
                bh[2 * p + 1][0] = r2; bh[2 * p + 1][1] = r3;
                ldsm4t(r0, r1, r2, r3, base + OFF_AL + boff[p][ka]);
                bl[2 * p][0] = r0; bl[2 * p][1] = r1;
                bl[2 * p + 1][0] = r2; bl[2 * p + 1][1] = r3;
            }
            #pragma unroll
            for (int ma = 0; ma < 2; ma++)
                #pragma unroll
                for (int na = 0; na < 4; na++) {
                    mma_bf16(acc[ma][na], ah[ma], bh[na]);
                    mma_bf16(acc[ma][na], ah[ma], bl[na]);
                    mma_bf16(acc[ma][na], al[ma], bh[na]);
                }
        }
        __syncthreads();
    }

    #pragma unroll
    for (int ma = 0; ma < 2; ma++) {
        int jA = j0 + wm * 32 + ma * 16 + gid;
        int jB = jA + 8;
        float bA = bias[jA], bB = bias[jB];
        #pragma unroll
        for (int na = 0; na < 4; na++) {
            int n = n0 + wn * 32 + na * 8 + tig * 2;
            float v0 = acc[ma][na][0] + bA;
            float v1 = acc[ma][na][1] + bA;
            float v2 = acc[ma][na][2] + bB;
            float v3 = acc[ma][na][3] + bB;
            if (EPI == 1) {
                v0 = gelu_f(v0); v1 = gelu_f(v1); v2 = gelu_f(v2); v3 = gelu_f(v3);
                __nv_bfloat16 h0,h1,h2,h3,l0,l1,l2,l3;
                splitbf(v0,h0,l0); splitbf(v1,h1,l1);
                splitbf(v2,h2,l2); splitbf(v3,h3,l3);
                ushort2 hA = { __bfloat16_as_ushort(h0), __bfloat16_as_ushort(h1) };
                ushort2 lA = { __bfloat16_as_ushort(l0), __bfloat16_as_ushort(l1) };
                ushort2 hB = { __bfloat16_as_ushort(h2), __bfloat16_as_ushort(h3) };
                ushort2 lB = { __bfloat16_as_ushort(l2), __bfloat16_as_ushort(l3) };
                *(ushort2*)&outh[(size_t)jA * NTOK + n] = hA;
                *(ushort2*)&outl[(size_t)jA * NTOK + n] = lA;
                *(ushort2*)&outh[(size_t)jB * NTOK + n] = hB;
                *(ushort2*)&outl[(size_t)jB * NTOK + n] = lB;
            } else {
                if (EPI == 2) {
                    float2 rA = *(const float2*)&Rres[(size_t)jA * NTOK + n];
                    float2 rB = *(const float2*)&Rres[(size_t)jB * NTOK + n];
                    v0 += rA.x; v1 += rA.y; v2 += rB.x; v3 += rB.y;
                }
                float2 oA = {v0, v1}, oB = {v2, v3};
                *(float2*)&outf[(size_t)jA * NTOK + n] = oA;
                *(float2*)&outf[(size_t)jB * NTOK + n] = oB;
            }
        }
    }
}

// ---------------- neighborhood attention: pillar-staged smem, two pass --------
// block = (ih, iw); 256 thr = 8 heads x 32 z. qkv [j][n], j: q 0-127, k 128-255, v 256-383.
// Each of the 9 (h,w) pillars (128 ch x 32 z fp32) staged via cp.async into a
// double buffer laid out [ch][z + 4 pad]; compute reads are conflict-free LDS.32.
#define NZP 36
__global__ __launch_bounds__(256)
void natten_kernel(const float* __restrict__ qkv,
                   const float* __restrict__ rpb,
                   __nv_bfloat16* __restrict__ outh,
                   __nv_bfloat16* __restrict__ outl)
{
    __shared__ __align__(16) float sbuf[2][CDIM * NZP];   // 2 x 18432 B

    const int tid  = threadIdx.x;
    const int lane = tid & 31;
    const int hh   = tid >> 5;
    const int ih   = blockIdx.x >> 5;
    const int iw   = blockIdx.x & 31;
    const int iz   = lane;
    const int n    = (ih * 32 + iw) * 32 + iz;

    int sh = ih - 1; sh = sh < 0 ? 0 : (sh > 29 ? 29 : sh);
    int sw = iw - 1; sw = sw < 0 ? 0 : (sw > 29 ? 29 : sw);
    int sz = iz - 1; sz = sz < 0 ? 0 : (sz > 29 ? 29 : sz);

    const int ch0 = tid >> 3;        // staging: channel handled by this thread (base)
    const int zq4 = (tid & 7) * 4;   // staging: z quad

    auto stage = [&](int p, int koff) {
        const int a = p / 3, b = p - a * 3;
        const int rowbase = ((sh + a) * 32 + (sw + b)) * 32;
        float* buf = sbuf[p & 1];
        #pragma unroll
        for (int i = 0; i < 4; i++) {
            int ch = ch0 + i * 32;
            cp16((uint32_t)__cvta_generic_to_shared(&buf[ch * NZP + zq4]),
                 &qkv[(size_t)(koff + ch) * NTOK + rowbase + zq4]);
        }
        cp_commit();
    };

    const float scale = 0.25f;
    float q[HD];
    #pragma unroll
    for (int d = 0; d < HD; d++)
        q[d] = qkv[(size_t)(hh * HD + d) * NTOK + n] * scale;

    // ---- pass 1: logits from k pillars ----
    float lg[27];
    float mx = -1e30f;
    stage(0, CDIM);
    for (int p = 0; p < 9; p++) {
        if (p + 1 < 9) { stage(p + 1, CDIM); cp_wait<1>(); }
        else           { cp_wait<0>(); }
        __syncthreads();
        const float* buf = sbuf[p & 1];
        const int a = p / 3, b = p - a * 3;
        const int rh = (sh + a) - ih + 2, rw = (sw + b) - iw + 2;
        #pragma unroll
        for (int c = 0; c < 3; c++) {
            const int zt = sz + c;
            float s = 0.0f;
            #pragma unroll
            for (int d = 0; d < HD; d++)
                s = fmaf(q[d], buf[(hh * HD + d) * NZP + zt], s);
            s += rpb[((hh * 5 + rh) * 5 + rw) * 5 + (zt - iz + 2)];
            lg[p * 3 + c] = s;
            mx = fmaxf(mx, s);
        }
        __syncthreads();
    }

    float denom = 0.0f;
    #pragma unroll
    for (int i = 0; i < 27; i++) { lg[i] = __expf(lg[i] - mx); denom += lg[i]; }
    const float inv = 1.0f / denom;

    // ---- pass 2: output from v pillars ----
    float o[HD];
    #pragma unroll
    for (int d = 0; d < HD; d++) o[d] = 0.0f;
    stage(0, 2 * CDIM);
    for (int p = 0; p < 9; p++) {
        if (p + 1 < 9) { stage(p + 1, 2 * CDIM); cp_wait<1>(); }
        else           { cp_wait<0>(); }
        __syncthreads();
        const float* buf = sbuf[p & 1];
        #pragma unroll
        for (int c = 0; c < 3; c++) {
            const int zt = sz + c;
            const float w = lg[p * 3 + c] * inv;
            #pragma unroll
            for (int d = 0; d < HD; d++)
                o[d] = fmaf(w, buf[(hh * HD + d) * NZP + zt], o[d]);
        }
        __syncthreads();
    }

    #pragma unroll
    for (int d = 0; d < HD; d++) {
        __nv_bfloat16 vh, vl;
        splitbf(o[d], vh, vl);
        outh[(size_t)(hh * HD + d) * NTOK + n] = vh;
        outl[(size_t)(hh * HD + d) * NTOK + n] = vl;
    }
}

// ---------------- instance norm: 3-phase, 1024-way parallel -------------------
__global__ __launch_bounds__(256)
void in_part_kernel(const float* __restrict__ in)
{
    const int c = blockIdx.x >> 3, seg = blockIdx.x & 7;
    const float4* p = (const float4*)(in + (size_t)c * NTOK + seg * 4096);
    float s = 0.0f, s2 = 0.0f;
    #pragma unroll
    for (int i = 0; i < 4; i++) {
        float4 v = p[threadIdx.x + i * 256];
        s  += v.x + v.y + v.z + v.w;
        s2 += v.x * v.x + v.y * v.y + v.z * v.z + v.w * v.w;
    }
    #pragma unroll
    for (int o = 16; o > 0; o >>= 1) {
        s  += __shfl_down_sync(0xffffffffu, s,  o);
        s2 += __shfl_down_sync(0xffffffffu, s2, o);
    }
    __shared__ float rs[8], rq[8];
    if ((threadIdx.x & 31) == 0) { rs[threadIdx.x >> 5] = s; rq[threadIdx.x >> 5] = s2; }
    __syncthreads();
    if (threadIdx.x == 0) {
        float ts = 0.0f, tq = 0.0f;
        #pragma unroll
        for (int i = 0; i < 8; i++) { ts += rs[i]; tq += rq[i]; }
        g_sum[c * 8 + seg] = ts;
        g_sq [c * 8 + seg] = tq;
    }
}

__global__ __launch_bounds__(128)
void in_fin_kernel()
{
    const int c = threadIdx.x;
    float s = 0.0f, s2 = 0.0f;
    #pragma unroll
    for (int i = 0; i < 8; i++) { s += g_sum[c * 8 + i]; s2 += g_sq[c * 8 + i]; }
    float m = s * (1.0f / NTOK);
    float v = s2 * (1.0f / NTOK) - m * m;
    g_mean[c] = m;
    g_rstd[c] = rsqrtf(v + 1e-5f);
}

template<int SPLIT>
__global__ __launch_bounds__(256)
void in_norm_kernel(const float* __restrict__ in, float* __restrict__ out,
                    __nv_bfloat16* __restrict__ oh, __nv_bfloat16* __restrict__ ol)
{
    const int c = blockIdx.x >> 3, seg = blockIdx.x & 7;
    const float m = g_mean[c], r = g_rstd[c];
    const size_t off = (size_t)c * NTOK + seg * 4096;
    const float4* p = (const float4*)(in + off);
    float4* qo = (float4*)(out + off);
    #pragma unroll
    for (int i = 0; i < 4; i++) {
        int idx = threadIdx.x + i * 256;
        float4 v = p[idx];
        v.x = (v.x - m) * r; v.y = (v.y - m) * r;
        v.z = (v.z - m) * r; v.w = (v.w - m) * r;
        qo[idx] = v;
        if (SPLIT) {
            __nv_bfloat16 h0,h1,h2,h3,l0,l1,l2,l3;
            splitbf(v.x,h0,l0); splitbf(v.y,h1,l1); splitbf(v.z,h2,l2); splitbf(v.w,h3,l3);
            ushort4 hv = { __bfloat16_as_ushort(h0), __bfloat16_as_ushort(h1),
                           __bfloat16_as_ushort(h2), __bfloat16_as_ushort(h3) };
            ushort4 lv = { __bfloat16_as_ushort(l0), __bfloat16_as_ushort(l1),
                           __bfloat16_as_ushort(l2), __bfloat16_as_ushort(l3) };
            ((ushort4*)(oh + off))[idx] = hv;
            ((ushort4*)(ol + off))[idx] = lv;
        }
    }
}

// ---------------- launch ------------------------------------------------------
extern "C" void kernel_launch(void* const* d_in, const int* in_sizes, int n_in,
                              void* d_out, int out_size)
{
    (void)in_sizes; (void)n_in; (void)out_size;
    const float* x      = (const float*)d_in[0];
    const float* w_qkv  = (const float*)d_in[1];
    const float* b_qkv  = (const float*)d_in[2];
    const float* rpb    = (const float*)d_in[3];
    const float* w_proj = (const float*)d_in[4];
    const float* b_proj = (const float*)d_in[5];
    const float* w_ffn1 = (const float*)d_in[6];
    const float* b_ffn1 = (const float*)d_in[7];
    const float* w_ffn2 = (const float*)d_in[8];
    const float* b_ffn2 = (const float*)d_in[9];
    float* out = (float*)d_out;

    float *qkv, *x5, *t, *y;
    __nv_bfloat16 *xh,*xl,*ah,*al,*th,*tl,*hh,*hl;
    __nv_bfloat16 *wqh,*wql,*wph,*wpl,*w1h,*w1l,*w2h,*w2l;
    cudaGetSymbolAddress((void**)&qkv, g_qkv);
    cudaGetSymbolAddress((void**)&x5,  g_x5);
    cudaGetSymbolAddress((void**)&t,   g_t);
    cudaGetSymbolAddress((void**)&y,   g_y);
    cudaGetSymbolAddress((void**)&xh,  g_xh);  cudaGetSymbolAddress((void**)&xl, g_xl);
    cudaGetSymbolAddress((void**)&ah,  g_ah);  cudaGetSymbolAddress((void**)&al, g_al);
    cudaGetSymbolAddress((void**)&th,  g_th);  cudaGetSymbolAddress((void**)&tl, g_tl);
    cudaGetSymbolAddress((void**)&hh,  g_hh);  cudaGetSymbolAddress((void**)&hl, g_hl);
    cudaGetSymbolAddress((void**)&wqh, g_wqh); cudaGetSymbolAddress((void**)&wql, g_wql);
    cudaGetSymbolAddress((void**)&wph, g_wph); cudaGetSymbolAddress((void**)&wpl, g_wpl);
    cudaGetSymbolAddress((void**)&w1h, g_w1h); cudaGetSymbolAddress((void**)&w1l, g_w1l);
    cudaGetSymbolAddress((void**)&w2h, g_w2h); cudaGetSymbolAddress((void**)&w2l, g_w2l);

    cudaFuncSetAttribute(gemm_tc<0>, cudaFuncAttributeMaxDynamicSharedMemorySize, SMEM_TOT);
    cudaFuncSetAttribute(gemm_tc<1>, cudaFuncAttributeMaxDynamicSharedMemorySize, SMEM_TOT);
    cudaFuncSetAttribute(gemm_tc<2>, cudaFuncAttributeMaxDynamicSharedMemorySize, SMEM_TOT);

    // 0) splits: x + all weights (one launch)
    split_kernel<<<4096, 256>>>(x, xh, xl, CDIM * NTOK / 4);
    wsplit_kernel<<<192, 256>>>(w_qkv, wqh, wql, w_proj, wph, wpl,
                                w_ffn1, w1h, w1l, w_ffn2, w2h, w2l);

    // 1) QKV -> fp32 [384][N]
    gemm_tc<0><<<dim3(NTOK / 128, 384 / 64), 256, SMEM_TOT>>>(
        xh, xl, wqh, wql, b_qkv, nullptr, qkv, nullptr, nullptr, CDIM);
    // 2) natten (pillar-staged smem) -> attn split bf16 [c][n]
    natten_kernel<<<1024, 256>>>(qkv, rpb, ah, al);
    // 3) proj -> x5 fp32
    gemm_tc<0><<<dim3(NTOK / 128, 128 / 64), 256, SMEM_TOT>>>(
        ah, al, wph, wpl, b_proj, nullptr, x5, nullptr, nullptr, CDIM);
    // 4) inorm1 -> t fp32 + split
    in_part_kernel<<<1024, 256>>>(x5);
    in_fin_kernel<<<1, 128>>>();
    in_norm_kernel<1><<<1024, 256>>>(x5, t, th, tl);
    // 5) FFN1 + gelu -> hidden split bf16
    gemm_tc<1><<<dim3(NTOK / 128, 512 / 64), 256, SMEM_TOT>>>(
        th, tl, w1h, w1l, b_ffn1, nullptr, nullptr, hh, hl, CDIM);
    // 6) FFN2 + residual(t) -> y fp32
    gemm_tc<2><<<dim3(NTOK / 128, 128 / 64), 256, SMEM_TOT>>>(
        hh, hl, w2h, w2l, b_ffn2, t, y, nullptr, nullptr, CF);
    // 7) final inorm -> out
    in_part_kernel<<<1024, 256>>>(y);
    in_fin_kernel<<<1, 128>>>();
    in_norm_kernel<0><<<1024, 256>>>(y, out, nullptr, nullptr);
}